// round 5
// baseline (speedup 1.0000x reference)
#include <cuda_runtime.h>

// B=512 rows, L=16 labels, N=8192 values. Single fused launch.
// loss = sum_{i,j} W[i,j] * S[i,j]
//   W[i,j] = sum_l inv[l] * [yt[i,l]==1] * [yt[j,l]==0],  inv[l]=1/((np*nn)^2 * 256)
//   S[i,j] = 0.5 * ( sum|t| + 256 - 16*sx[i] + 16*sx[j] ),  t = 1 - x[i,c] + x[j,d]
// Block 0 does one-time setup and releases a flag; all blocks then process one
// 16x16 row tile (1 thread per row pair, 256 element pairs via packed f32x2).
// Last block (atomic ticket) reduces the 1024 partials and writes the output.

#define NROW 512
#define NL   16
#define TI   16
#define GB   (NROW / TI)          // 32
#define NBLK (GB * GB)            // 1024
#define XJP  17                   // padded stride for transposed xj tile

__device__ unsigned int g_pm[NROW];
__device__ float        g_sx[NROW];
__device__ float        g_tlo[256];
__device__ float        g_thi[256];
__device__ float        g_part[NBLK];
__device__ unsigned int g_cnt  = 0;
__device__ unsigned int g_flag = 0;

// ---- packed f32x2 helpers -------------------------------------------------
__device__ __forceinline__ unsigned long long pk2(float lo, float hi) {
    unsigned long long r;
    asm("mov.b64 %0, {%1, %2};" : "=l"(r) : "f"(lo), "f"(hi));
    return r;
}
__device__ __forceinline__ unsigned long long addx2(unsigned long long a,
                                                    unsigned long long b) {
    unsigned long long r;
    asm("add.rn.f32x2 %0, %1, %2;" : "=l"(r) : "l"(a), "l"(b));
    return r;
}
__device__ __forceinline__ void unpk2(unsigned long long v, float& lo, float& hi) {
    asm("mov.b64 {%0, %1}, %2;" : "=f"(lo), "=f"(hi) : "l"(v));
}

__global__ void __launch_bounds__(256) k_all(const int* __restrict__ yt,
                                             const float* __restrict__ yp,
                                             float* __restrict__ out, int n_out) {
    __shared__ float    xi[TI * NL];          // i-tile, row-major
    __shared__ float    xjT[NL * XJP];        // j-tile, transposed + padded
    __shared__ float    tlo_s[256], thi_s[256];
    __shared__ unsigned pmI[TI], nmJ[TI];
    __shared__ float    sxI[TI], sxJ[TI];
    __shared__ float    red[256];
    __shared__ float    wsum[8];
    __shared__ int      cnt[NL];
    __shared__ float    inv_s[NL];
    __shared__ int      is_last;

    const int b   = blockIdx.x;
    const int bi  = b & (GB - 1);
    const int bj  = b >> 5;
    const int tid = threadIdx.x;
    const int lid = tid & 31;

    if (b == 0) {
        // ------------- one-time setup (2 rows per thread) -------------------
        if (tid < NL) cnt[tid] = 0;
        __syncthreads();

        const int r0 = 2 * tid;
        unsigned m0 = 0, m1 = 0;
        float sx0 = 0.0f, sx1 = 0.0f;
        {
            const int4*   y4 = (const int4*)(yt + r0 * NL);
            const float4* p4 = (const float4*)(yp + r0 * NL);
            #pragma unroll
            for (int q = 0; q < 4; q++) {
                int4 v = y4[q];
                if (v.x) m0 |= 1u << (4 * q + 0);
                if (v.y) m0 |= 1u << (4 * q + 1);
                if (v.z) m0 |= 1u << (4 * q + 2);
                if (v.w) m0 |= 1u << (4 * q + 3);
                float4 f = p4[q];
                sx0 += (f.x + f.y) + (f.z + f.w);
            }
            #pragma unroll
            for (int q = 0; q < 4; q++) {
                int4 v = y4[4 + q];
                if (v.x) m1 |= 1u << (4 * q + 0);
                if (v.y) m1 |= 1u << (4 * q + 1);
                if (v.z) m1 |= 1u << (4 * q + 2);
                if (v.w) m1 |= 1u << (4 * q + 3);
                float4 f = p4[4 + q];
                sx1 += (f.x + f.y) + (f.z + f.w);
            }
        }
        g_pm[r0] = m0;  g_pm[r0 + 1] = m1;
        g_sx[r0] = sx0; g_sx[r0 + 1] = sx1;

        #pragma unroll
        for (int l = 0; l < NL; l++) {
            unsigned b0 = __ballot_sync(0xffffffffu, (m0 >> l) & 1u);
            unsigned b1 = __ballot_sync(0xffffffffu, (m1 >> l) & 1u);
            if (lid == 0) atomicAdd(&cnt[l], __popc(b0) + __popc(b1));
        }
        __syncthreads();

        if (tid < NL) {
            int np = cnt[tid], nn = NROW - np;
            float d = (float)np * (float)nn;        // <= 2^18, exact in fp32
            inv_s[tid] = (np > 0 && nn > 0) ? 1.0f / (d * d * 256.0f) : 0.0f;
        }
        __syncthreads();

        {
            float lo = 0.0f, hi = 0.0f;
            #pragma unroll
            for (int l = 0; l < 8; l++) {
                if ((tid >> l) & 1) { lo += inv_s[l]; hi += inv_s[8 + l]; }
            }
            tlo_s[tid] = lo;  thi_s[tid] = hi;
            g_tlo[tid] = lo;  g_thi[tid] = hi;
        }
        __threadfence();
        __syncthreads();
        if (tid == 0) atomicExch(&g_flag, 1u);
    } else {
        if (tid == 0) {
            while (*(volatile unsigned int*)&g_flag == 0u) __nanosleep(64);
        }
        __syncthreads();
        __threadfence();
        tlo_s[tid] = g_tlo[tid];
        thi_s[tid] = g_thi[tid];
    }

    // ---------------- per-block tile staging --------------------------------
    xi[tid] = yp[bi * (TI * NL) + tid];
    // transpose j tile: element (jrow = tid>>4, d = tid&15)
    xjT[(tid & 15) * XJP + (tid >> 4)] = yp[bj * (TI * NL) + tid];
    if (tid < TI) {
        pmI[tid] = g_pm[bi * TI + tid];
        sxI[tid] = g_sx[bi * TI + tid];
    } else if (tid < 2 * TI) {
        int j = tid - TI;
        nmJ[j] = (~g_pm[bj * TI + j]) & 0xFFFFu;
        sxJ[j] = g_sx[bj * TI + j];
    }
    __syncthreads();

    // ---------------- main 16x16-pair loop ----------------------------------
    const int il = tid >> 4;
    const int jl = tid & 15;

    unsigned long long ci2[8];
    #pragma unroll
    for (int k = 0; k < 8; k++)
        ci2[k] = pk2(1.0f - xi[il * NL + 2 * k], 1.0f - xi[il * NL + 2 * k + 1]);

    float xq[NL];
    #pragma unroll
    for (int d = 0; d < NL; d++) xq[d] = xjT[d * XJP + jl];   // conflict-free

    const unsigned long long ABSM = 0x7FFFFFFF7FFFFFFFULL;
    unsigned long long sa0 = 0, sa1 = 0;

    #pragma unroll
    for (int d = 0; d < NL; d++) {
        unsigned long long xq2 = pk2(xq[d], xq[d]);
        #pragma unroll
        for (int k = 0; k < 8; k += 2) {
            unsigned long long t0 = addx2(ci2[k],     xq2) & ABSM;
            unsigned long long t1 = addx2(ci2[k + 1], xq2) & ABSM;
            sa0 = addx2(sa0, t0);
            sa1 = addx2(sa1, t1);
        }
    }

    float a0, a1, c0, c1;
    unpk2(sa0, a0, a1);
    unpk2(sa1, c0, c1);
    float s_abs = (a0 + a1) + (c0 + c1);
    float sum_t = 256.0f - 16.0f * sxI[il] + 16.0f * sxJ[jl];

    unsigned mask = pmI[il] & nmJ[jl];
    float W = tlo_s[mask & 255u] + thi_s[mask >> 8];
    float contrib = W * 0.5f * (s_abs + sum_t);

    // ---------------- deterministic reduction -------------------------------
    #pragma unroll
    for (int o = 16; o > 0; o >>= 1)
        contrib += __shfl_down_sync(0xffffffffu, contrib, o);
    if (lid == 0) wsum[tid >> 5] = contrib;
    __syncthreads();
    if (tid == 0) {
        float v = ((wsum[0] + wsum[1]) + (wsum[2] + wsum[3]))
                + ((wsum[4] + wsum[5]) + (wsum[6] + wsum[7]));
        g_part[b] = v;
        __threadfence();
        unsigned t = atomicAdd(&g_cnt, 1u);
        is_last = (t == NBLK - 1);
    }
    __syncthreads();

    // ---------------- last block: final reduce + output ---------------------
    if (is_last) {
        __threadfence();
        float v = g_part[tid] + g_part[tid + 256] + g_part[tid + 512] + g_part[tid + 768];
        red[tid] = v;
        __syncthreads();
        #pragma unroll
        for (int s = 128; s > 0; s >>= 1) {
            if (tid < s) red[tid] += red[tid + s];
            __syncthreads();
        }
        if (tid == 0) {
            out[0]  = red[0];
            g_cnt   = 0;     // reset for next graph replay
            g_flag  = 0;
        }
        for (int i = tid + 1; i < n_out; i += 256) out[i] = 0.0f;
    }
}

extern "C" void kernel_launch(void* const* d_in, const int* in_sizes, int n_in,
                              void* d_out, int out_size) {
    const int*   yt  = (const int*)d_in[0];    // y_true int32 [512*16]
    const float* yp  = (const float*)d_in[1];  // y_pred fp32  [512*16]
    float*       out = (float*)d_out;

    k_all<<<NBLK, 256>>>(yt, yp, out, out_size);
}

// round 6
// speedup vs baseline: 1.2821x; 1.2821x over previous
#include <cuda_runtime.h>

// B=512 rows, L=16 labels, N=8192 values. Single kernel, no inter-block spin.
// loss = sum_l inv[l] * A_l,   inv[l] = 1/((np*nn)^2 * 256)
// A_l  = sum_{i: yt[i,l]=1} sum_{j: yt[j,l]=0} S[i,j]
// S[i,j] = 0.5*( sum|t| + 256 - 16*sx_i + 16*sx_j ),  t = 1 - x[i,c] + x[j,d]
// Blocks accumulate per-label partials (no dependency on global setup);
// block 0 additionally computes g_inv[16]; the ticketed last block combines.

#define NROW 512
#define NL   16
#define TI   16
#define GB   (NROW / TI)          // 32
#define NBLK (GB * GB)            // 1024
#define XJP  17                   // padded stride, transposed xj tile
#define ASP  257                  // padded stride, per-label scatter array

__device__ float        g_inv[NL];
__device__ float        g_pl[NBLK * NL];   // per-block per-label partials
__device__ unsigned int g_cnt = 0;

// ---- packed f32x2 helpers -------------------------------------------------
__device__ __forceinline__ unsigned long long pk2(float lo, float hi) {
    unsigned long long r;
    asm("mov.b64 %0, {%1, %2};" : "=l"(r) : "f"(lo), "f"(hi));
    return r;
}
__device__ __forceinline__ unsigned long long addx2(unsigned long long a,
                                                    unsigned long long b) {
    unsigned long long r;
    asm("add.rn.f32x2 %0, %1, %2;" : "=l"(r) : "l"(a), "l"(b));
    return r;
}
__device__ __forceinline__ void unpk2(unsigned long long v, float& lo, float& hi) {
    asm("mov.b64 {%0, %1}, %2;" : "=f"(lo), "=f"(hi) : "l"(v));
}

__global__ void __launch_bounds__(256) k_all(const int* __restrict__ yt,
                                             const float* __restrict__ yp,
                                             float* __restrict__ out, int n_out) {
    __shared__ float    xi[TI * NL];        // i-tile, row-major
    __shared__ float    xjT[NL * XJP];      // j-tile, transposed + padded
    __shared__ float    As[NL * ASP];       // per-label scatter [l][tid]
    __shared__ float    A2[NL * 17];        // stage-2 partials [l][chunk]
    __shared__ float    wfin[NL];
    __shared__ unsigned pmI[TI], nmJ[TI];
    __shared__ float    sxI[TI], sxJ[TI];
    __shared__ int      cnt[NL];
    __shared__ int      is_last;

    const int b   = blockIdx.x;
    const int bi  = b & (GB - 1);
    const int bj  = b >> 5;
    const int tid = threadIdx.x;

    // ---- stage prediction tiles -------------------------------------------
    xi[tid] = yp[bi * (TI * NL) + tid];
    xjT[(tid & 15) * XJP + (tid >> 4)] = yp[bj * (TI * NL) + tid];

    // ---- block 0 only: per-label n_pos -> g_inv (all 256 threads) ----------
    if (b == 0) {
        if (tid < NL) cnt[tid] = 0;
        __syncthreads();
        const int r0 = 2 * tid;
        unsigned m0 = 0, m1 = 0;
        const int4* y4 = (const int4*)(yt + r0 * NL);
        #pragma unroll
        for (int q = 0; q < 4; q++) {
            int4 v = y4[q];
            if (v.x) m0 |= 1u << (4 * q + 0);
            if (v.y) m0 |= 1u << (4 * q + 1);
            if (v.z) m0 |= 1u << (4 * q + 2);
            if (v.w) m0 |= 1u << (4 * q + 3);
        }
        #pragma unroll
        for (int q = 0; q < 4; q++) {
            int4 v = y4[4 + q];
            if (v.x) m1 |= 1u << (4 * q + 0);
            if (v.y) m1 |= 1u << (4 * q + 1);
            if (v.z) m1 |= 1u << (4 * q + 2);
            if (v.w) m1 |= 1u << (4 * q + 3);
        }
        #pragma unroll
        for (int l = 0; l < NL; l++) {
            unsigned b0 = __ballot_sync(0xffffffffu, (m0 >> l) & 1u);
            unsigned b1 = __ballot_sync(0xffffffffu, (m1 >> l) & 1u);
            if ((tid & 31) == 0) atomicAdd(&cnt[l], __popc(b0) + __popc(b1));
        }
        __syncthreads();
        if (tid < NL) {
            int np = cnt[tid], nn = NROW - np;
            float d = (float)np * (float)nn;          // <= 2^18, exact in fp32
            g_inv[tid] = (np > 0 && nn > 0) ? 1.0f / (d * d * 256.0f) : 0.0f;
        }
    }

    // ---- per-block row masks (32 threads, coalesced) ------------------------
    if (tid < 2 * TI) {
        int row = (tid < TI) ? (bi * TI + tid) : (bj * TI + (tid - TI));
        unsigned m = 0;
        const int4* y4 = (const int4*)(yt + row * NL);
        #pragma unroll
        for (int q = 0; q < 4; q++) {
            int4 v = y4[q];
            if (v.x) m |= 1u << (4 * q + 0);
            if (v.y) m |= 1u << (4 * q + 1);
            if (v.z) m |= 1u << (4 * q + 2);
            if (v.w) m |= 1u << (4 * q + 3);
        }
        if (tid < TI) pmI[tid] = m;
        else          nmJ[tid - TI] = (~m) & 0xFFFFu;
    }
    __syncthreads();

    // ---- per-row sums from staged tiles -------------------------------------
    if (tid < TI) {
        float s = 0.0f;
        #pragma unroll
        for (int c = 0; c < NL; c++) s += xi[tid * NL + c];
        sxI[tid] = s;
    } else if (tid < 2 * TI) {
        int j = tid - TI;
        float s = 0.0f;
        #pragma unroll
        for (int c = 0; c < NL; c++) s += xjT[c * XJP + j];
        sxJ[j] = s;
    }
    __syncthreads();

    // ---- main 16x16-pair loop ------------------------------------------------
    const int il = tid >> 4;
    const int jl = tid & 15;

    unsigned long long ci2[8];
    #pragma unroll
    for (int k = 0; k < 8; k++)
        ci2[k] = pk2(1.0f - xi[il * NL + 2 * k], 1.0f - xi[il * NL + 2 * k + 1]);

    const unsigned long long ABSM = 0x7FFFFFFF7FFFFFFFULL;
    unsigned long long sa0 = 0, sa1 = 0;

    #pragma unroll
    for (int d = 0; d < NL; d++) {
        float xq = xjT[d * XJP + jl];          // conflict-free broadcast
        unsigned long long xq2 = pk2(xq, xq);
        #pragma unroll
        for (int k = 0; k < 8; k += 2) {
            unsigned long long t0 = addx2(ci2[k],     xq2) & ABSM;
            unsigned long long t1 = addx2(ci2[k + 1], xq2) & ABSM;
            sa0 = addx2(sa0, t0);
            sa1 = addx2(sa1, t1);
        }
    }

    float a0, a1, c0, c1;
    unpk2(sa0, a0, a1);
    unpk2(sa1, c0, c1);
    float s_abs = (a0 + a1) + (c0 + c1);
    float S = 0.5f * (s_abs + (256.0f - 16.0f * sxI[il] + 16.0f * sxJ[jl]));

    // ---- per-label scatter + two-stage block reduction -----------------------
    unsigned mask = pmI[il] & nmJ[jl];
    #pragma unroll
    for (int l = 0; l < NL; l++)
        As[l * ASP + tid] = ((mask >> l) & 1u) ? S : 0.0f;
    __syncthreads();

    {
        const int l = tid & 15, ch = tid >> 4;
        float a = 0.0f;
        #pragma unroll
        for (int k = 0; k < 16; k++) a += As[l * ASP + ch * 16 + k];
        A2[l * 17 + ch] = a;
    }
    __syncthreads();

    if (tid < NL) {
        float s = 0.0f;
        #pragma unroll
        for (int c = 0; c < 16; c++) s += A2[tid * 17 + c];
        g_pl[b * NL + tid] = s;
        __threadfence();               // publish this thread's writes (incl. g_inv for b==0)
    }
    __syncthreads();

    if (tid == 0) {
        unsigned t = atomicAdd(&g_cnt, 1u);
        is_last = (t == NBLK - 1);
    }
    __syncthreads();

    // ---- last block: global per-label reduce + weighted combine --------------
    if (is_last) {
        __threadfence();
        const int l = tid & 15, ch = tid >> 4;
        float a = 0.0f;
        for (int k = 0; k < 64; k++)                    // fixed order: deterministic
            a += g_pl[(ch * 64 + k) * NL + l];
        A2[l * 17 + ch] = a;
        __syncthreads();
        if (tid < NL) {
            float s = 0.0f;
            #pragma unroll
            for (int c = 0; c < 16; c++) s += A2[tid * 17 + c];
            wfin[tid] = s * g_inv[tid];
        }
        __syncthreads();
        if (tid == 0) {
            float loss = 0.0f;
            #pragma unroll
            for (int l2 = 0; l2 < NL; l2++) loss += wfin[l2];
            out[0] = loss;
            g_cnt  = 0;                 // reset for next graph replay
        }
        for (int i = tid + 1; i < n_out; i += 256) out[i] = 0.0f;
    }
}

extern "C" void kernel_launch(void* const* d_in, const int* in_sizes, int n_in,
                              void* d_out, int out_size) {
    const int*   yt  = (const int*)d_in[0];    // y_true int32 [512*16]
    const float* yp  = (const float*)d_in[1];  // y_pred fp32  [512*16]
    float*       out = (float*)d_out;

    k_all<<<NBLK, 256>>>(yt, yp, out, out_size);
}